// round 12
// baseline (speedup 1.0000x reference)
#include <cuda_runtime.h>
#include <cstdint>

// Problem constants (fixed by the reference)
#define BB 8
#define TT 512
#define DD 512
#define D4 (DD / 4)       // 128 float4 per frame
#define MAX_LEN 7680      // TT * 15
#define FR 64             // output frames per CTA
#define NW (FR / 16)      // 4 gather waves

// ---------------------------------------------------------------------------
// Single fused kernel. Grid (120, 8), block 512.
//   Phase 1: shfl block-scan of max(dur,1); thread t keeps [start,end).
//   Phase 2: scatter — thread t writes t into sidx for frames it owns inside
//            this CTA's 64-frame window (frames past total keep -1).
//   Phase 3: four 16-frame gather waves: (128 lanes x 4 groups) x 4 frames,
//            float4 loads + plain stores, zero-fill where sidx < 0.
// ---------------------------------------------------------------------------
__global__ void __launch_bounds__(512) fused_expand_kernel(
    const float4* __restrict__ feat,  // (B, T, D/4)
    const int*    __restrict__ dur,   // (B, T)
    float4*       __restrict__ out)   // (B, MAX_LEN, D/4)
{
    __shared__ int wsum[16];
    __shared__ int sidx[FR];

    const int b     = blockIdx.y;
    const int base0 = blockIdx.x * FR;
    const int tid   = threadIdx.x;          // 0..511
    const int lane5 = tid & 31, w = tid >> 5;

    // Pre-init sidx (ordered before the scatter by the scan barriers).
    if (tid < FR) sidx[tid] = -1;

    // ---- Phase 1: inclusive scan of clamped durations ----
    int v = __ldg(&dur[b * TT + tid]);
    v = (v < 1) ? 1 : v;
    int x = v;
#pragma unroll
    for (int o = 1; o < 32; o <<= 1) {
        int y = __shfl_up_sync(0xFFFFFFFFu, x, o);
        if (lane5 >= o) x += y;
    }
    if (lane5 == 31) wsum[w] = x;
    __syncthreads();
    if (w == 0) {
        int s = (lane5 < 16) ? wsum[lane5] : 0;
#pragma unroll
        for (int o = 1; o < 16; o <<= 1) {
            int y = __shfl_up_sync(0xFFFFFFFFu, s, o);
            if (lane5 >= o) s += y;
        }
        if (lane5 < 16) wsum[lane5] = s;
    }
    __syncthreads();
    const int end   = ((w > 0) ? wsum[w - 1] : 0) + x;  // inclusive cumsum
    const int start = end - v;

    // ---- Phase 2: scatter phoneme id into this CTA's frame window ----
    {
        int lo = (start > base0) ? start : base0;
        const int hi = (end < base0 + FR) ? end : (base0 + FR);
        for (int i = lo; i < hi; i++) sidx[i - base0] = tid;
    }
    __syncthreads();

    // ---- Phase 3: gather-expand, NW 16-frame waves ----
    const int y    = tid >> 7;   // 0..3
    const int lane = tid & 127;  // 0..127
    const float4* __restrict__ fb = feat + (size_t)b * TT * D4;
    const float4 zero = make_float4(0.f, 0.f, 0.f, 0.f);

#pragma unroll
    for (int half = 0; half < NW; half++) {
        const int fbase = base0 + 16 * half + y;
        float4* __restrict__ ob =
            out + ((size_t)b * MAX_LEN + fbase) * D4 + lane;

        int idx[4];
#pragma unroll
        for (int j = 0; j < 4; j++)
            idx[j] = sidx[16 * half + y + 4 * j];     // SMEM broadcast

        float4 val[4];
#pragma unroll
        for (int j = 0; j < 4; j++)
            val[j] = (idx[j] >= 0) ? __ldg(fb + (size_t)idx[j] * D4 + lane)
                                   : zero;
#pragma unroll
        for (int j = 0; j < 4; j++)
            ob[(size_t)4 * j * D4] = val[j];          // plain store
    }
}

// ---------------------------------------------------------------------------
// Launch
// ---------------------------------------------------------------------------
extern "C" void kernel_launch(void* const* d_in, const int* in_sizes, int n_in,
                              void* d_out, int out_size) {
    const float4* feat = (const float4*)d_in[0];  // features (8,512,512) f32
    const int*    dur  = (const int*)d_in[1];     // durations (8,512) i32
    float4*       out  = (float4*)d_out;          // (8,7680,512) f32

    (void)in_sizes; (void)n_in; (void)out_size;

    dim3 grid(MAX_LEN / FR, BB, 1);
    fused_expand_kernel<<<grid, 512>>>(feat, dur, out);
}

// round 15
// speedup vs baseline: 1.2333x; 1.2333x over previous
#include <cuda_runtime.h>
#include <cstdint>

// Problem constants (fixed by the reference)
#define BB 8
#define TT 512
#define DD 512
#define D4 (DD / 4)       // 128 float4 per frame
#define MAX_LEN 7680      // TT * 15
#define FR 32             // output frames per CTA

// ---------------------------------------------------------------------------
// Single fused kernel. Grid (240, 8), block 512.
//   Phase 1: shfl block-scan of max(dur,1); thread t keeps [start,end).
//   Phase 2: scatter — thread t writes t into sidx for frames it owns inside
//            this CTA's 32-frame window (frames past total keep -1).
//   Phase 3: gather-expand, 8 frames per thread: ALL 8 gather loads issued
//            up front (MLP=8), then all 8 streaming stores.
// ---------------------------------------------------------------------------
__global__ void __launch_bounds__(512) fused_expand_kernel(
    const float4* __restrict__ feat,  // (B, T, D/4)
    const int*    __restrict__ dur,   // (B, T)
    float4*       __restrict__ out)   // (B, MAX_LEN, D/4)
{
    __shared__ int wsum[16];
    __shared__ int sidx[FR];

    const int b     = blockIdx.y;
    const int base0 = blockIdx.x * FR;
    const int tid   = threadIdx.x;          // 0..511
    const int lane5 = tid & 31, w = tid >> 5;

    // Pre-init sidx (ordered before the scatter by the scan barriers).
    if (tid < FR) sidx[tid] = -1;

    // ---- Phase 1: inclusive scan of clamped durations ----
    int v = __ldg(&dur[b * TT + tid]);
    v = (v < 1) ? 1 : v;
    int x = v;
#pragma unroll
    for (int o = 1; o < 32; o <<= 1) {
        int y = __shfl_up_sync(0xFFFFFFFFu, x, o);
        if (lane5 >= o) x += y;
    }
    if (lane5 == 31) wsum[w] = x;
    __syncthreads();
    if (w == 0) {
        int s = (lane5 < 16) ? wsum[lane5] : 0;
#pragma unroll
        for (int o = 1; o < 16; o <<= 1) {
            int y = __shfl_up_sync(0xFFFFFFFFu, s, o);
            if (lane5 >= o) s += y;
        }
        if (lane5 < 16) wsum[lane5] = s;
    }
    __syncthreads();
    const int end   = ((w > 0) ? wsum[w - 1] : 0) + x;  // inclusive cumsum
    const int start = end - v;

    // ---- Phase 2: scatter phoneme id into this CTA's frame window ----
    {
        int lo = (start > base0) ? start : base0;
        const int hi = (end < base0 + FR) ? end : (base0 + FR);
        for (int i = lo; i < hi; i++) sidx[i - base0] = tid;
    }
    __syncthreads();

    // ---- Phase 3: gather-expand, 8 frames/thread, front-batched loads ----
    const int y    = tid >> 7;   // 0..3
    const int lane = tid & 127;  // 0..127
    const float4* __restrict__ fb = feat + (size_t)b * TT * D4;
    const float4 zero = make_float4(0.f, 0.f, 0.f, 0.f);

    // Frames handled by this thread: base0 + y + 4*j, j = 0..7.
    int idx[8];
#pragma unroll
    for (int j = 0; j < 8; j++)
        idx[j] = sidx[y + 4 * j];                     // SMEM broadcasts

    float4 val[8];
#pragma unroll
    for (int j = 0; j < 8; j++)                       // all LDGs up front
        val[j] = (idx[j] >= 0) ? __ldg(fb + (size_t)idx[j] * D4 + lane)
                               : zero;

    float4* __restrict__ ob =
        out + ((size_t)b * MAX_LEN + base0 + y) * D4 + lane;
#pragma unroll
    for (int j = 0; j < 8; j++)                       // then all stores
        __stcs(&ob[(size_t)4 * j * D4], val[j]);
}

// ---------------------------------------------------------------------------
// Launch
// ---------------------------------------------------------------------------
extern "C" void kernel_launch(void* const* d_in, const int* in_sizes, int n_in,
                              void* d_out, int out_size) {
    const float4* feat = (const float4*)d_in[0];  // features (8,512,512) f32
    const int*    dur  = (const int*)d_in[1];     // durations (8,512) i32
    float4*       out  = (float4*)d_out;          // (8,7680,512) f32

    (void)in_sizes; (void)n_in; (void)out_size;

    dim3 grid(MAX_LEN / FR, BB, 1);
    fused_expand_kernel<<<grid, 512>>>(feat, dur, out);
}